// round 5
// baseline (speedup 1.0000x reference)
#include <cuda_runtime.h>
#include <math.h>

#define T_ALL 128
#define T_STEPS 127
#define BSZ 256
#define DD 512
#define HH 1024
#define OO 20
#define KC 320                     // Eigen gebp kc cap (panel boundary)

__device__ __constant__ float c_ALPHA = 0.95122942450071400909f; // fp32(exp(-1/20))
__device__ __constant__ float c_KAPPA = 0.95122942450071400909f;
#define THRv 1.0f

// ---- scratch (device globals; no allocation allowed) ----
__device__ float g_xin[(size_t)T_STEPS * BSZ * HH];   // 133 MB: x @ w_in^T
__device__ float g_v[BSZ * HH];
__device__ float g_z0[BSZ * HH];
__device__ float g_z1[BSZ * HH];
__device__ float g_vo[BSZ * OO];
__device__ float g_WT[HH * HH];                       // WT[j][h] = w_rec_eff[h][j] (diag zeroed)

// ============================================================
// prep: transposed, diagonal-zeroed recurrent weights
// ============================================================
__global__ void __launch_bounds__(256) prep_k(const float* __restrict__ w_rec) {
    int idx = blockIdx.x * 256 + threadIdx.x;
    int stride = gridDim.x * 256;
    for (int i = idx; i < HH * HH; i += stride) {
        int j = i / HH, h = i % HH;
        g_WT[i] = (h == j) ? 0.0f : w_rec[(size_t)h * HH + j];
    }
}

// ============================================================
// init: zero state, zero output row 0
// ============================================================
__global__ void __launch_bounds__(256) init_k(float* __restrict__ out) {
    int i = blockIdx.x * blockDim.x + threadIdx.x;
    int stride = gridDim.x * blockDim.x;
    for (int idx = i; idx < BSZ * HH; idx += stride) {
        g_v[idx] = 0.f;
        g_z0[idx] = 0.f;
    }
    for (int idx = i; idx < BSZ * OO; idx += stride) {
        g_vo[idx] = 0.f;
        out[idx] = 0.f;
    }
}

// ============================================================
// input GEMM, Eigen gebp semantics:
//   per element: fma chains ascending d within kc=320 panels,
//   panel sums folded left-to-right:  tot = (p0 + p1)
// M = 32512, N = 1024, K = 512; 64x64 tile, BK=16, 4x4 microtile
// ============================================================
__global__ void __launch_bounds__(256) in_gemm(const float* __restrict__ x,
                                               const float* __restrict__ w_in) {
    __shared__ float As[16][64];
    __shared__ float Bs[16][64];
    const int tid = threadIdx.x;
    const int m0 = blockIdx.y * 64;
    const int n0 = blockIdx.x * 64;

    const int lr = tid >> 2;        // 0..63
    const int lc = (tid & 3) * 4;   // 0,4,8,12
    const int tm = (tid >> 4) * 4;  // 0..60
    const int tn = (tid & 15) * 4;  // 0..60

    const float* Ab = x + (size_t)(m0 + lr) * DD + lc;
    const float* Bb = w_in + (size_t)(n0 + lr) * DD + lc;

    float tot[4][4] = {};
    float acc[4][4] = {};

    for (int k0 = 0; k0 < DD; k0 += 16) {
        float4 a = *(const float4*)(Ab + k0);
        float4 b = *(const float4*)(Bb + k0);
        As[lc + 0][lr] = a.x; As[lc + 1][lr] = a.y;
        As[lc + 2][lr] = a.z; As[lc + 3][lr] = a.w;
        Bs[lc + 0][lr] = b.x; Bs[lc + 1][lr] = b.y;
        Bs[lc + 2][lr] = b.z; Bs[lc + 3][lr] = b.w;
        __syncthreads();
#pragma unroll
        for (int d = 0; d < 16; d++) {          // ascending k within tile
            float ar[4], br[4];
#pragma unroll
            for (int i = 0; i < 4; i++) ar[i] = As[d][tm + i];
#pragma unroll
            for (int j = 0; j < 4; j++) br[j] = Bs[d][tn + j];
#pragma unroll
            for (int i = 0; i < 4; i++)
#pragma unroll
                for (int j = 0; j < 4; j++)
                    acc[i][j] = __fmaf_rn(ar[i], br[j], acc[i][j]);
        }
        __syncthreads();
        if (((k0 + 16) % KC) == 0) {            // panel boundary (k=320)
#pragma unroll
            for (int i = 0; i < 4; i++)
#pragma unroll
                for (int j = 0; j < 4; j++) {
                    tot[i][j] = __fadd_rn(tot[i][j], acc[i][j]);
                    acc[i][j] = 0.f;
                }
        }
    }

#pragma unroll
    for (int i = 0; i < 4; i++) {
        float* dst = g_xin + (size_t)(m0 + tm + i) * HH + n0 + tn;
#pragma unroll
        for (int j = 0; j < 4; j++)
            dst[j] = __fadd_rn(tot[i][j], acc[i][j]);   // fold tail panel [320,512)
    }
}

// ============================================================
// recurrent step, Eigen gebp semantics:
//   rec = ((p0 + p1) + p2) + p3, panels [0,320),[320,640),[640,960),[960,1024)
//   each panel = ascending-k fma chain
//   v = fma(alpha, v, rec); v += xin; v -= z;   z' = v > THR
// tile 16(b) x 64(h), BK=16, 256 threads, 1x4 microtile; grid (16,16)
// ============================================================
__global__ void __launch_bounds__(256) rec_step(float* __restrict__ dummy, int t) {
    const float* __restrict__ zin = (t & 1) ? g_z1 : g_z0;
    float* __restrict__ zout      = (t & 1) ? g_z0 : g_z1;

    __shared__ float Zs[16][17];   // [k][b]
    __shared__ float Ws[16][68];   // [k][h]

    const int tid = threadIdx.x;
    const int b0 = blockIdx.x * 16;
    const int h0 = blockIdx.y * 64;

    const int lk = tid & 15;        // k within tile for Z load
    const int lb = tid >> 4;        // b within tile for Z load
    const int wk = tid >> 4;        // k for W load
    const int wh = (tid & 15) * 4;  // h for W load

    const int b_t = tid >> 4;       // output b (0..15)
    const int h_t = (tid & 15) * 4; // output h (0,4,..,60)

    float tot[4] = {};
    float acc[4] = {};

    for (int k0 = 0; k0 < HH; k0 += 16) {
        Zs[lk][lb] = zin[(size_t)(b0 + lb) * HH + k0 + lk];
        float4 w4 = *(const float4*)(g_WT + (size_t)(k0 + wk) * HH + h0 + wh);
        Ws[wk][wh + 0] = w4.x; Ws[wk][wh + 1] = w4.y;
        Ws[wk][wh + 2] = w4.z; Ws[wk][wh + 3] = w4.w;
        __syncthreads();
#pragma unroll
        for (int d = 0; d < 16; d++) {          // ascending k
            float zv = Zs[d][b_t];
#pragma unroll
            for (int j = 0; j < 4; j++)
                acc[j] = __fmaf_rn(zv, Ws[d][h_t + j], acc[j]);
        }
        __syncthreads();
        if (((k0 + 16) % KC) == 0) {            // boundaries at 320, 640, 960
#pragma unroll
            for (int j = 0; j < 4; j++) {
                tot[j] = __fadd_rn(tot[j], acc[j]);
                acc[j] = 0.f;
            }
        }
    }
#pragma unroll
    for (int j = 0; j < 4; j++)
        tot[j] = __fadd_rn(tot[j], acc[j]);     // tail panel [960,1024)

    const size_t idx = (size_t)(b0 + b_t) * HH + h0 + h_t;
    const float4 vv = *(const float4*)(g_v + idx);
    const float4 zz = *(const float4*)(zin + idx);
    const float4 xi = *(const float4*)(g_xin + (size_t)t * BSZ * HH + idx);

    float vinA[4] = {vv.x, vv.y, vv.z, vv.w};
    float zinA[4] = {zz.x, zz.y, zz.z, zz.w};
    float xinA[4] = {xi.x, xi.y, xi.z, xi.w};
    float vO[4], zO[4];

#pragma unroll
    for (int j = 0; j < 4; j++) {
        float vn = __fmaf_rn(c_ALPHA, vinA[j], tot[j]);   // fma(alpha, v, rec)
        vn = __fadd_rn(vn, xinA[j]);                      // + x@Win^T
        vn = __fsub_rn(vn, zinA[j]);                      // - z  (z*1.0 simplified)
        vO[j] = vn;
        zO[j] = (vn > THRv) ? 1.0f : 0.0f;
    }
    *(float4*)(g_v + idx)  = make_float4(vO[0], vO[1], vO[2], vO[3]);
    *(float4*)(zout + idx) = make_float4(zO[0], zO[1], zO[2], zO[3]);
}

// ============================================================
// output step: dot = ascending-h fma chain (vo path can't flip spikes)
// vo = fma(kappa, vo, dot)
// ============================================================
__global__ void __launch_bounds__(256) out_step(const float* __restrict__ w_out,
                                                float* __restrict__ out, int t) {
    const float* __restrict__ zn = (t & 1) ? g_z0 : g_z1;  // z written by rec_step(t)
    const int b = blockIdx.x;
    const int tid = threadIdx.x;

    __shared__ float sz[HH];
#pragma unroll
    for (int i = 0; i < HH / 256; i++)
        sz[tid + i * 256] = zn[(size_t)b * HH + tid + i * 256];
    __syncthreads();

    if (tid < OO) {
        const float* wr = w_out + (size_t)tid * HH;
        float acc = 0.f;
#pragma unroll 4
        for (int h = 0; h < HH; h++)
            acc = __fmaf_rn(sz[h], wr[h], acc);
        float vo = __fmaf_rn(c_KAPPA, g_vo[b * OO + tid], acc);
        g_vo[b * OO + tid] = vo;
        out[((size_t)(t + 1) * BSZ + b) * OO + tid] = vo;
    }
}

// ============================================================
// softmax over last dim (O=20), in place. one warp per row.
// ============================================================
__global__ void __launch_bounds__(128) softmax_k(float* __restrict__ out) {
    const int row = blockIdx.x * 4 + (threadIdx.x >> 5);
    const int lane = threadIdx.x & 31;
    float* pr = out + (size_t)row * OO;

    float v = (lane < OO) ? pr[lane] : -INFINITY;
    float m = v;
#pragma unroll
    for (int off = 16; off > 0; off >>= 1)
        m = fmaxf(m, __shfl_xor_sync(0xffffffff, m, off));
    float e = (lane < OO) ? expf(v - m) : 0.f;
    float s = e;
#pragma unroll
    for (int off = 16; off > 0; off >>= 1)
        s += __shfl_xor_sync(0xffffffff, s, off);
    if (lane < OO) pr[lane] = e / s;
}

// ============================================================
extern "C" void kernel_launch(void* const* d_in, const int* in_sizes, int n_in,
                              void* d_out, int out_size) {
    const float* x     = (const float*)d_in[0];  // [128,256,512]
    const float* w_in  = (const float*)d_in[1];  // [1024,512]
    const float* w_rec = (const float*)d_in[2];  // [1024,1024]
    const float* w_out = (const float*)d_in[3];  // [20,1024]
    float* out = (float*)d_out;                  // [128,256,20]

    prep_k<<<512, 256>>>(w_rec);
    init_k<<<256, 256>>>(out);
    in_gemm<<<dim3(HH / 64, (T_STEPS * BSZ) / 64), 256>>>(x, w_in);

    for (int t = 0; t < T_STEPS; t++) {
        rec_step<<<dim3(BSZ / 16, HH / 64), 256>>>(nullptr, t);
        out_step<<<BSZ, 256>>>(w_out, out, t);
    }

    softmax_k<<<(T_ALL * BSZ) / 4, 128>>>(out);
}

// round 6
// speedup vs baseline: 1.5843x; 1.5843x over previous
#include <cuda_runtime.h>
#include <math.h>

#define T_ALL 128
#define T_STEPS 127
#define BSZ 256
#define DD 512
#define HH 1024
#define OO 20
#define KC 320                     // Eigen gebp kc panel boundary (confirmed R5)

__device__ __constant__ float c_ALPHA = 0.95122942450071400909f; // fp32(exp(-1/20))
__device__ __constant__ float c_KAPPA = 0.95122942450071400909f;
#define THRv 1.0f

// ---- scratch (device globals; no allocation allowed) ----
__device__ float g_xin[(size_t)T_STEPS * BSZ * HH];   // 133 MB
__device__ float g_v[BSZ * HH];
__device__ float g_z0[BSZ * HH];
__device__ float g_z1[BSZ * HH];
__device__ float g_vo[BSZ * OO];
__device__ float g_WT[HH * HH];                       // WT[j][h] = w_rec_eff[h][j] (diag zeroed)

// ============================================================
// prep: transposed, diagonal-zeroed recurrent weights
// ============================================================
__global__ void __launch_bounds__(256) prep_k(const float* __restrict__ w_rec) {
    int idx = blockIdx.x * 256 + threadIdx.x;
    int stride = gridDim.x * 256;
    for (int i = idx; i < HH * HH; i += stride) {
        int j = i / HH, h = i % HH;
        g_WT[i] = (h == j) ? 0.0f : w_rec[(size_t)h * HH + j];
    }
}

// ============================================================
// init: zero state, zero output row 0
// ============================================================
__global__ void __launch_bounds__(256) init_k(float* __restrict__ out) {
    int i = blockIdx.x * blockDim.x + threadIdx.x;
    int stride = gridDim.x * blockDim.x;
    for (int idx = i; idx < BSZ * HH; idx += stride) {
        g_v[idx] = 0.f;
        g_z0[idx] = 0.f;
    }
    for (int idx = i; idx < BSZ * OO; idx += stride) {
        g_vo[idx] = 0.f;
        out[idx] = 0.f;
    }
}

// ============================================================
// input GEMM (bit-exact chain, kc=320 fold):
// 128m x 64n tile, BK=16, 256 threads, 8x4 microtile
// grid (16, 254)
// ============================================================
__global__ void __launch_bounds__(256) in_gemm(const float* __restrict__ x,
                                               const float* __restrict__ w_in) {
    __shared__ float As[16][132];   // [k][m], padded
    __shared__ float Bs[16][68];    // [k][n], padded
    const int tid = threadIdx.x;
    const int m0 = blockIdx.y * 128;
    const int n0 = blockIdx.x * 64;

    const int kk4 = (tid & 3) * 4;      // k group for loads
    const int lm  = tid >> 2;           // 0..63
    const int tm  = (tid >> 4) * 8;     // 0..120
    const int tn  = (tid & 15) * 4;     // 0..60

    float tot[8][4] = {};
    float acc[8][4] = {};

    for (int k0 = 0; k0 < DD; k0 += 16) {
        // load A tile: 16k x 128m (2 passes of 64 m)
#pragma unroll
        for (int p = 0; p < 2; p++) {
            int m = lm + p * 64;
            float4 a = *(const float4*)(x + (size_t)(m0 + m) * DD + k0 + kk4);
            As[kk4 + 0][m] = a.x; As[kk4 + 1][m] = a.y;
            As[kk4 + 2][m] = a.z; As[kk4 + 3][m] = a.w;
        }
        // load B tile: 16k x 64n (1 pass)
        {
            float4 b = *(const float4*)(w_in + (size_t)(n0 + lm) * DD + k0 + kk4);
            Bs[kk4 + 0][lm] = b.x; Bs[kk4 + 1][lm] = b.y;
            Bs[kk4 + 2][lm] = b.z; Bs[kk4 + 3][lm] = b.w;
        }
        __syncthreads();
#pragma unroll
        for (int d = 0; d < 16; d++) {          // ascending k
            float ar[8], br[4];
            *(float4*)(ar + 0) = *(const float4*)(&As[d][tm + 0]);
            *(float4*)(ar + 4) = *(const float4*)(&As[d][tm + 4]);
            *(float4*)(br)     = *(const float4*)(&Bs[d][tn]);
#pragma unroll
            for (int i = 0; i < 8; i++)
#pragma unroll
                for (int j = 0; j < 4; j++)
                    acc[i][j] = __fmaf_rn(ar[i], br[j], acc[i][j]);
        }
        __syncthreads();
        if (k0 + 16 == KC) {                    // panel boundary at k=320
#pragma unroll
            for (int i = 0; i < 8; i++)
#pragma unroll
                for (int j = 0; j < 4; j++) {
                    tot[i][j] = __fadd_rn(tot[i][j], acc[i][j]);
                    acc[i][j] = 0.f;
                }
        }
    }

#pragma unroll
    for (int i = 0; i < 8; i++) {
        float* dst = g_xin + (size_t)(m0 + tm + i) * HH + n0 + tn;
        float4 o;
        o.x = __fadd_rn(tot[i][0], acc[i][0]);
        o.y = __fadd_rn(tot[i][1], acc[i][1]);
        o.z = __fadd_rn(tot[i][2], acc[i][2]);
        o.w = __fadd_rn(tot[i][3], acc[i][3]);
        *(float4*)dst = o;
    }
}

// ============================================================
// recurrent step (bit-exact chain, folds at 320/640/960):
// 32b x 64h tile, BK=32, 256 threads, 2x4 microtile
// grid (8, 16) = 128 blocks
// ============================================================
__global__ void __launch_bounds__(256) rec_step(int t) {
    const float* __restrict__ zin = (t & 1) ? g_z1 : g_z0;
    float* __restrict__ zout      = (t & 1) ? g_z0 : g_z1;

    __shared__ float Zs[32][34];   // [k][b], padded (even stride for LDS.64)
    __shared__ float Ws[32][68];   // [k][h], padded

    const int tid = threadIdx.x;
    const int b0 = blockIdx.x * 32;
    const int h0 = blockIdx.y * 64;

    const int zk = tid & 31;        // k for Z load
    const int zb = tid >> 5;        // b base for Z load (8 per pass)
    const int wk = tid >> 4;        // k base for W load (16 per pass)
    const int wh = (tid & 15) * 4;  // h for W load

    const int tb = tid >> 4;        // 0..15 -> b pair
    const int th = (tid & 15) * 4;  // 0..60 -> h quad

    float tot[2][4] = {};
    float acc[2][4] = {};

    for (int k0 = 0; k0 < HH; k0 += 32) {
        // Z tile: 32k x 32b
#pragma unroll
        for (int p = 0; p < 4; p++) {
            int b = zb + p * 8;
            Zs[zk][b] = zin[(size_t)(b0 + b) * HH + k0 + zk];
        }
        // W tile: 32k x 64h
#pragma unroll
        for (int p = 0; p < 2; p++) {
            int k = wk + p * 16;
            float4 w4 = *(const float4*)(g_WT + (size_t)(k0 + k) * HH + h0 + wh);
            Ws[k][wh + 0] = w4.x; Ws[k][wh + 1] = w4.y;
            Ws[k][wh + 2] = w4.z; Ws[k][wh + 3] = w4.w;
        }
        __syncthreads();
#pragma unroll
        for (int d = 0; d < 32; d++) {          // ascending k
            float2 zv = *(const float2*)(&Zs[d][tb * 2]);
            float4 w4 = *(const float4*)(&Ws[d][th]);
            float wr[4] = {w4.x, w4.y, w4.z, w4.w};
#pragma unroll
            for (int j = 0; j < 4; j++) {
                acc[0][j] = __fmaf_rn(zv.x, wr[j], acc[0][j]);
                acc[1][j] = __fmaf_rn(zv.y, wr[j], acc[1][j]);
            }
        }
        __syncthreads();
        if (((k0 + 32) % KC) == 0) {            // boundaries at 320, 640, 960
#pragma unroll
            for (int i = 0; i < 2; i++)
#pragma unroll
                for (int j = 0; j < 4; j++) {
                    tot[i][j] = __fadd_rn(tot[i][j], acc[i][j]);
                    acc[i][j] = 0.f;
                }
        }
    }

    const float* xin = g_xin + (size_t)t * BSZ * HH;
#pragma unroll
    for (int i = 0; i < 2; i++) {
        const size_t idx = (size_t)(b0 + tb * 2 + i) * HH + h0 + th;
        const float4 vv = *(const float4*)(g_v + idx);
        const float4 zz = *(const float4*)(zin + idx);
        const float4 xi = *(const float4*)(xin + idx);
        float vin[4] = {vv.x, vv.y, vv.z, vv.w};
        float zi[4]  = {zz.x, zz.y, zz.z, zz.w};
        float xv[4]  = {xi.x, xi.y, xi.z, xi.w};
        float vO[4], zO[4];
#pragma unroll
        for (int j = 0; j < 4; j++) {
            float rec = __fadd_rn(tot[i][j], acc[i][j]);       // tail panel fold
            float vn = __fmaf_rn(c_ALPHA, vin[j], rec);        // fma(alpha, v, rec)
            vn = __fadd_rn(vn, xv[j]);                         // + xin
            vn = __fsub_rn(vn, zi[j]);                         // - z
            vO[j] = vn;
            zO[j] = (vn > THRv) ? 1.0f : 0.0f;
        }
        *(float4*)(g_v + idx)  = make_float4(vO[0], vO[1], vO[2], vO[3]);
        *(float4*)(zout + idx) = make_float4(zO[0], zO[1], zO[2], zO[3]);
    }
}

// ============================================================
// output step (vo path: no bit-exactness needed — parallelize)
// one block per b; 20 outputs x 8 h-chunks of 128; smem reduce
// ============================================================
__global__ void __launch_bounds__(256) out_step(const float* __restrict__ w_out,
                                                float* __restrict__ out, int t) {
    const float* __restrict__ zn = (t & 1) ? g_z0 : g_z1;  // z written by rec_step(t)
    const int b = blockIdx.x;
    const int tid = threadIdx.x;

    __shared__ float sz[HH];
    __shared__ float sp[OO][9];
#pragma unroll
    for (int i = 0; i < HH / 256; i++)
        sz[tid + i * 256] = zn[(size_t)b * HH + tid + i * 256];
    __syncthreads();

    if (tid < OO * 8) {
        const int o = tid >> 3;
        const int c = tid & 7;
        const float* wr = w_out + (size_t)o * HH + c * 128;
        const float* zr = sz + c * 128;
        float acc = 0.f;
#pragma unroll 8
        for (int h = 0; h < 128; h++)
            acc = __fmaf_rn(zr[h], wr[h], acc);
        sp[o][c] = acc;
    }
    __syncthreads();

    if (tid < OO) {
        float s = sp[tid][0];
#pragma unroll
        for (int c = 1; c < 8; c++) s += sp[tid][c];
        float vo = __fmaf_rn(c_KAPPA, g_vo[b * OO + tid], s);
        g_vo[b * OO + tid] = vo;
        out[((size_t)(t + 1) * BSZ + b) * OO + tid] = vo;
    }
}

// ============================================================
// softmax over last dim (O=20), in place. one warp per row.
// ============================================================
__global__ void __launch_bounds__(128) softmax_k(float* __restrict__ out) {
    const int row = blockIdx.x * 4 + (threadIdx.x >> 5);
    const int lane = threadIdx.x & 31;
    float* pr = out + (size_t)row * OO;

    float v = (lane < OO) ? pr[lane] : -INFINITY;
    float m = v;
#pragma unroll
    for (int off = 16; off > 0; off >>= 1)
        m = fmaxf(m, __shfl_xor_sync(0xffffffff, m, off));
    float e = (lane < OO) ? expf(v - m) : 0.f;
    float s = e;
#pragma unroll
    for (int off = 16; off > 0; off >>= 1)
        s += __shfl_xor_sync(0xffffffff, s, off);
    if (lane < OO) pr[lane] = e / s;
}

// ============================================================
extern "C" void kernel_launch(void* const* d_in, const int* in_sizes, int n_in,
                              void* d_out, int out_size) {
    const float* x     = (const float*)d_in[0];  // [128,256,512]
    const float* w_in  = (const float*)d_in[1];  // [1024,512]
    const float* w_rec = (const float*)d_in[2];  // [1024,1024]
    const float* w_out = (const float*)d_in[3];  // [20,1024]
    float* out = (float*)d_out;                  // [128,256,20]

    prep_k<<<512, 256>>>(w_rec);
    init_k<<<256, 256>>>(out);
    in_gemm<<<dim3(HH / 64, (T_STEPS * BSZ) / 128), 256>>>(x, w_in);

    for (int t = 0; t < T_STEPS; t++) {
        rec_step<<<dim3(BSZ / 32, HH / 64), 256>>>(t);
        out_step<<<BSZ, 256>>>(w_out, out, t);
    }

    softmax_k<<<(T_ALL * BSZ) / 4, 128>>>(out);
}

// round 7
// speedup vs baseline: 3.1133x; 1.9651x over previous
#include <cuda_runtime.h>
#include <math.h>

#define T_ALL 128
#define T_STEPS 127
#define BSZ 256
#define DD 512
#define HH 1024
#define OO 20
#define KC 320                     // Eigen gebp kc panel boundary (confirmed R5)

__device__ __constant__ float c_ALPHA = 0.95122942450071400909f; // fp32(exp(-1/20))
__device__ __constant__ float c_KAPPA = 0.95122942450071400909f;
#define THRv 1.0f

// ---- scratch (device globals; no allocation allowed) ----
__device__ float g_xin[(size_t)T_STEPS * BSZ * HH];   // 133 MB
__device__ float g_v[BSZ * HH];
__device__ float g_vo[BSZ * OO];
__device__ float g_WT[HH * HH];        // WT[j][h] = w_rec_eff[h][j] (diag zeroed)
__device__ int   g_act[BSZ][HH];       // ascending active-j lists
__device__ int   g_po[BSZ][5];         // per-panel cumulative offsets into g_act

// ============================================================
// prep: transposed, diagonal-zeroed recurrent weights
// ============================================================
__global__ void __launch_bounds__(256) prep_k(const float* __restrict__ w_rec) {
    int idx = blockIdx.x * 256 + threadIdx.x;
    int stride = gridDim.x * 256;
    for (int i = idx; i < HH * HH; i += stride) {
        int j = i / HH, h = i % HH;
        g_WT[i] = (h == j) ? 0.0f : w_rec[(size_t)h * HH + j];
    }
}

// ============================================================
// init: zero state, empty active lists, zero output row 0
// ============================================================
__global__ void __launch_bounds__(256) init_k(float* __restrict__ out) {
    int i = blockIdx.x * blockDim.x + threadIdx.x;
    int stride = gridDim.x * blockDim.x;
    for (int idx = i; idx < BSZ * HH; idx += stride) g_v[idx] = 0.f;
    for (int idx = i; idx < BSZ * OO; idx += stride) {
        g_vo[idx] = 0.f;
        out[idx] = 0.f;
    }
    for (int idx = i; idx < BSZ * 5; idx += stride) ((int*)g_po)[idx] = 0;
}

// ============================================================
// input GEMM (bit-exact chain, kc=320 fold via global staging):
// 128m x 128n tile, BK=8, 256 threads, 8x8 microtile
// panel [0,320) staged to g_xin at boundary; folded back at end.
// grid (8, 254)
// ============================================================
__global__ void __launch_bounds__(256) in_gemm(const float* __restrict__ x,
                                               const float* __restrict__ w_in) {
    __shared__ float As[8][128];
    __shared__ float Bs[8][128];
    const int tid = threadIdx.x;
    const int m0 = blockIdx.y * 128;
    const int n0 = blockIdx.x * 128;

    const int lr = tid >> 1;            // 0..127 (row within tile)
    const int lk = (tid & 1) * 4;       // 0 or 4 (k quad)
    const int tm = (tid >> 4) * 8;      // 0..120
    const int tn = (tid & 15) * 8;      // 0..120

    float acc[8][8] = {};

    for (int k0 = 0; k0 < DD; k0 += 8) {
        float4 a = *(const float4*)(x + (size_t)(m0 + lr) * DD + k0 + lk);
        float4 b = *(const float4*)(w_in + (size_t)(n0 + lr) * DD + k0 + lk);
        As[lk + 0][lr] = a.x; As[lk + 1][lr] = a.y;
        As[lk + 2][lr] = a.z; As[lk + 3][lr] = a.w;
        Bs[lk + 0][lr] = b.x; Bs[lk + 1][lr] = b.y;
        Bs[lk + 2][lr] = b.z; Bs[lk + 3][lr] = b.w;
        __syncthreads();
#pragma unroll
        for (int d = 0; d < 8; d++) {           // ascending k
            float ar[8], br[8];
            *(float4*)(ar + 0) = *(const float4*)(&As[d][tm + 0]);
            *(float4*)(ar + 4) = *(const float4*)(&As[d][tm + 4]);
            *(float4*)(br + 0) = *(const float4*)(&Bs[d][tn + 0]);
            *(float4*)(br + 4) = *(const float4*)(&Bs[d][tn + 4]);
#pragma unroll
            for (int i = 0; i < 8; i++)
#pragma unroll
                for (int j = 0; j < 8; j++)
                    acc[i][j] = __fmaf_rn(ar[i], br[j], acc[i][j]);
        }
        __syncthreads();
        if (k0 + 8 == KC) {                     // stage panel 0 to global
#pragma unroll
            for (int i = 0; i < 8; i++) {
                float* dst = g_xin + (size_t)(m0 + tm + i) * HH + n0 + tn;
                *(float4*)(dst + 0) = *(float4*)(&acc[i][0]);
                *(float4*)(dst + 4) = *(float4*)(&acc[i][4]);
#pragma unroll
                for (int j = 0; j < 8; j++) acc[i][j] = 0.f;
            }
        }
    }

    // fold: xin = fadd(p0, p1)
#pragma unroll
    for (int i = 0; i < 8; i++) {
        float* dst = g_xin + (size_t)(m0 + tm + i) * HH + n0 + tn;
        float4 p0a = *(const float4*)(dst + 0);
        float4 p0b = *(const float4*)(dst + 4);
        float4 oa, ob;
        oa.x = __fadd_rn(p0a.x, acc[i][0]); oa.y = __fadd_rn(p0a.y, acc[i][1]);
        oa.z = __fadd_rn(p0a.z, acc[i][2]); oa.w = __fadd_rn(p0a.w, acc[i][3]);
        ob.x = __fadd_rn(p0b.x, acc[i][4]); ob.y = __fadd_rn(p0b.y, acc[i][5]);
        ob.z = __fadd_rn(p0b.z, acc[i][6]); ob.w = __fadd_rn(p0b.w, acc[i][7]);
        *(float4*)(dst + 0) = oa;
        *(float4*)(dst + 4) = ob;
    }
}

// ============================================================
// fused sparse step: block per batch row b (grid = 256).
// rec[h] = sequential fadd over active j (ascending) of WT[j][h],
//          panel folds at j=320/640/960  == bit-exact dense chain (z in {0,1})
// v = fma(alpha,v,rec) + xin - z_prev ; z = v > THR
// build next ascending active list (ordered block scan) + panel offsets
// output projection over new list (order-free), vo update, write out[t+1]
// ============================================================
__global__ void __launch_bounds__(256) step_k(const float* __restrict__ w_out,
                                              float* __restrict__ out, int t) {
    const int b = blockIdx.x;
    const int tid = threadIdx.x;
    const int lane = tid & 31, wid = tid >> 5;

    __shared__ int s_act[HH];
    __shared__ int s_new[HH];
    __shared__ int s_po[5];
    __shared__ int s_wsum[8], s_woff[8];
    __shared__ int s_total;
    __shared__ float s_red[OO][9];

    if (tid < 5) s_po[tid] = g_po[b][tid];
    __syncthreads();
    const int pc = s_po[4];
    for (int i = tid; i < pc; i += 256) s_act[i] = g_act[b][i];
    __syncthreads();

    const int h4 = tid * 4;

    // ---- sparse recurrent sum: 4 independent exact chains, per-panel fold ----
    float tot0 = 0.f, tot1 = 0.f, tot2 = 0.f, tot3 = 0.f;
#pragma unroll 1
    for (int p = 0; p < 4; p++) {
        const int beg = s_po[p], end = s_po[p + 1];
        float a0 = 0.f, a1 = 0.f, a2 = 0.f, a3 = 0.f;
#pragma unroll 4
        for (int i = beg; i < end; i++) {
            const int j = s_act[i];
            const float4 w = *(const float4*)(g_WT + (size_t)j * HH + h4);
            a0 = __fadd_rn(a0, w.x);
            a1 = __fadd_rn(a1, w.y);
            a2 = __fadd_rn(a2, w.z);
            a3 = __fadd_rn(a3, w.w);
        }
        tot0 = __fadd_rn(tot0, a0);   // ((p0+p1)+p2)+p3, with 0+p0 == p0 exact
        tot1 = __fadd_rn(tot1, a1);
        tot2 = __fadd_rn(tot2, a2);
        tot3 = __fadd_rn(tot3, a3);
    }

    // ---- v update ----
    const size_t idx = (size_t)b * HH + h4;
    const float4 vv = *(const float4*)(g_v + idx);
    const float4 xi = *(const float4*)(g_xin + (size_t)t * BSZ * HH + idx);

    const float zp0 = (vv.x > THRv) ? 1.f : 0.f;
    const float zp1 = (vv.y > THRv) ? 1.f : 0.f;
    const float zp2 = (vv.z > THRv) ? 1.f : 0.f;
    const float zp3 = (vv.w > THRv) ? 1.f : 0.f;

    float vn0 = __fsub_rn(__fadd_rn(__fmaf_rn(c_ALPHA, vv.x, tot0), xi.x), zp0);
    float vn1 = __fsub_rn(__fadd_rn(__fmaf_rn(c_ALPHA, vv.y, tot1), xi.y), zp1);
    float vn2 = __fsub_rn(__fadd_rn(__fmaf_rn(c_ALPHA, vv.z, tot2), xi.z), zp2);
    float vn3 = __fsub_rn(__fadd_rn(__fmaf_rn(c_ALPHA, vv.w, tot3), xi.w), zp3);

    *(float4*)(g_v + idx) = make_float4(vn0, vn1, vn2, vn3);

    const bool z0 = vn0 > THRv, z1 = vn1 > THRv, z2 = vn2 > THRv, z3 = vn3 > THRv;
    const int cnt = (int)z0 + (int)z1 + (int)z2 + (int)z3;

    // ---- ordered block scan -> compact ascending active list ----
    int s = cnt;
#pragma unroll
    for (int o = 1; o < 32; o <<= 1) {
        int v = __shfl_up_sync(0xffffffffu, s, o);
        if (lane >= o) s += v;
    }
    if (lane == 31) s_wsum[wid] = s;
    __syncthreads();
    if (wid == 0 && lane < 8) {
        int v = s_wsum[lane];
        int sc = v;
#pragma unroll
        for (int o = 1; o < 8; o <<= 1) {
            int u = __shfl_up_sync(0xffu, sc, o);
            if (lane >= o) sc += u;
        }
        s_woff[lane] = sc - v;               // exclusive warp offset
        if (lane == 7) s_total = sc;
    }
    __syncthreads();

    int wofs = s_woff[wid] + s - cnt;        // exclusive global offset
    int o = wofs;
    if (z0) s_new[o++] = h4 + 0;
    if (z1) s_new[o++] = h4 + 1;
    if (z2) s_new[o++] = h4 + 2;
    if (z3) s_new[o++] = h4 + 3;

    const int incl = s_woff[wid] + s;        // inclusive count through this thread
    if (tid == 79)  g_po[b][1] = incl;       // h < 320
    if (tid == 159) g_po[b][2] = incl;       // h < 640
    if (tid == 239) g_po[b][3] = incl;       // h < 960
    if (tid == 255) { g_po[b][4] = incl; g_po[b][0] = 0; }
    __syncthreads();

    const int total = s_total;
    for (int i = tid; i < total; i += 256) g_act[b][i] = s_new[i];

    // ---- output projection over new spikes (order-free) ----
    if (tid < OO * 8) {
        const int oo = tid >> 3, c = tid & 7;
        const float* wr = w_out + (size_t)oo * HH;
        float acc = 0.f;
        for (int i = c; i < total; i += 8)
            acc += wr[s_new[i]];
        s_red[oo][c] = acc;
    }
    __syncthreads();
    if (tid < OO) {
        float ssum = s_red[tid][0];
#pragma unroll
        for (int c = 1; c < 8; c++) ssum += s_red[tid][c];
        float vo = __fmaf_rn(c_KAPPA, g_vo[b * OO + tid], ssum);
        g_vo[b * OO + tid] = vo;
        out[((size_t)(t + 1) * BSZ + b) * OO + tid] = vo;
    }
}

// ============================================================
// softmax over last dim (O=20), in place. one warp per row.
// ============================================================
__global__ void __launch_bounds__(128) softmax_k(float* __restrict__ out) {
    const int row = blockIdx.x * 4 + (threadIdx.x >> 5);
    const int lane = threadIdx.x & 31;
    float* pr = out + (size_t)row * OO;

    float v = (lane < OO) ? pr[lane] : -INFINITY;
    float m = v;
#pragma unroll
    for (int off = 16; off > 0; off >>= 1)
        m = fmaxf(m, __shfl_xor_sync(0xffffffff, m, off));
    float e = (lane < OO) ? expf(v - m) : 0.f;
    float s = e;
#pragma unroll
    for (int off = 16; off > 0; off >>= 1)
        s += __shfl_xor_sync(0xffffffff, s, off);
    if (lane < OO) pr[lane] = e / s;
}

// ============================================================
extern "C" void kernel_launch(void* const* d_in, const int* in_sizes, int n_in,
                              void* d_out, int out_size) {
    const float* x     = (const float*)d_in[0];  // [128,256,512]
    const float* w_in  = (const float*)d_in[1];  // [1024,512]
    const float* w_rec = (const float*)d_in[2];  // [1024,1024]
    const float* w_out = (const float*)d_in[3];  // [20,1024]
    float* out = (float*)d_out;                  // [128,256,20]

    prep_k<<<512, 256>>>(w_rec);
    init_k<<<256, 256>>>(out);
    in_gemm<<<dim3(HH / 128, (T_STEPS * BSZ) / 128), 256>>>(x, w_in);

    for (int t = 0; t < T_STEPS; t++)
        step_k<<<BSZ, 256>>>(w_out, out, t);

    softmax_k<<<(T_ALL * BSZ) / 4, 128>>>(out);
}

// round 8
// speedup vs baseline: 3.4719x; 1.1152x over previous
#include <cuda_runtime.h>
#include <math.h>

#define T_ALL 128
#define T_STEPS 127
#define BSZ 256
#define DD 512
#define HH 1024
#define OO 20
#define KC 320                     // Eigen gebp kc panel boundary (confirmed R5)
#define TCHUNK 16                  // timesteps per in_gemm chunk

__device__ __constant__ float c_ALPHA = 0.95122942450071400909f; // fp32(exp(-1/20))
__device__ __constant__ float c_KAPPA = 0.95122942450071400909f;
#define THRv 1.0f

// ---- scratch (device globals; no allocation allowed) ----
__device__ float g_xin[(size_t)T_STEPS * BSZ * HH];   // 133 MB
__device__ float g_WT[HH * HH];        // WT[j][h] = w_rec_eff[h][j] (diag zeroed)
__device__ int   g_ready;              // chunk-completion flag (monotonic per launch)

// ============================================================
__global__ void set_flag(int v) { g_ready = v; }
__global__ void marker(int v)   { atomicExch(&g_ready, v); }

// ============================================================
// prep: transposed, diagonal-zeroed recurrent weights
// ============================================================
__global__ void __launch_bounds__(256) prep_k(const float* __restrict__ w_rec) {
    int idx = blockIdx.x * 256 + threadIdx.x;
    int stride = gridDim.x * 256;
    for (int i = idx; i < HH * HH; i += stride) {
        int j = i / HH, h = i % HH;
        g_WT[i] = (h == j) ? 0.0f : w_rec[(size_t)h * HH + j];
    }
}

// ============================================================
// input GEMM chunk (bit-exact chain, kc=320 fold via global staging):
// 128m x 128n tile, BK=8 double-buffered, 256 threads, 8x8 microtile
// ============================================================
__global__ void __launch_bounds__(256) in_gemm(const float* __restrict__ x,
                                               const float* __restrict__ w_in,
                                               int m_base) {
    __shared__ float As[2][8][128];
    __shared__ float Bs[2][8][128];
    const int tid = threadIdx.x;
    const int m0 = m_base + blockIdx.y * 128;
    const int n0 = blockIdx.x * 128;

    const int lr = tid >> 1;            // 0..127
    const int lk = (tid & 1) * 4;       // 0 or 4
    const int tm = (tid >> 4) * 8;      // 0..120
    const int tn = (tid & 15) * 8;      // 0..120

    const float* Ap = x + (size_t)(m0 + lr) * DD + lk;
    const float* Bp = w_in + (size_t)(n0 + lr) * DD + lk;

    float4 a  = *(const float4*)(Ap);
    float4 bb = *(const float4*)(Bp);
    As[0][lk + 0][lr] = a.x;  As[0][lk + 1][lr] = a.y;
    As[0][lk + 2][lr] = a.z;  As[0][lk + 3][lr] = a.w;
    Bs[0][lk + 0][lr] = bb.x; Bs[0][lk + 1][lr] = bb.y;
    Bs[0][lk + 2][lr] = bb.z; Bs[0][lk + 3][lr] = bb.w;
    __syncthreads();

    float acc[8][8] = {};
    int s = 0;

    for (int k0 = 0; k0 < DD; k0 += 8) {
        const int nk = k0 + 8;
        if (nk < DD) {                  // prefetch next tile into registers
            a  = *(const float4*)(Ap + nk);
            bb = *(const float4*)(Bp + nk);
        }
#pragma unroll
        for (int d = 0; d < 8; d++) {   // ascending k
            float ar[8], br[8];
            *(float4*)(ar + 0) = *(const float4*)(&As[s][d][tm + 0]);
            *(float4*)(ar + 4) = *(const float4*)(&As[s][d][tm + 4]);
            *(float4*)(br + 0) = *(const float4*)(&Bs[s][d][tn + 0]);
            *(float4*)(br + 4) = *(const float4*)(&Bs[s][d][tn + 4]);
#pragma unroll
            for (int i = 0; i < 8; i++)
#pragma unroll
                for (int j = 0; j < 8; j++)
                    acc[i][j] = __fmaf_rn(ar[i], br[j], acc[i][j]);
        }
        if (nk == KC) {                 // stage panel 0 to global, restart chain
#pragma unroll
            for (int i = 0; i < 8; i++) {
                float* dst = g_xin + (size_t)(m0 + tm + i) * HH + n0 + tn;
                *(float4*)(dst + 0) = *(float4*)(&acc[i][0]);
                *(float4*)(dst + 4) = *(float4*)(&acc[i][4]);
#pragma unroll
                for (int j = 0; j < 8; j++) acc[i][j] = 0.f;
            }
        }
        if (nk < DD) {                  // store prefetched tile to other buffer
            As[s ^ 1][lk + 0][lr] = a.x;  As[s ^ 1][lk + 1][lr] = a.y;
            As[s ^ 1][lk + 2][lr] = a.z;  As[s ^ 1][lk + 3][lr] = a.w;
            Bs[s ^ 1][lk + 0][lr] = bb.x; Bs[s ^ 1][lk + 1][lr] = bb.y;
            Bs[s ^ 1][lk + 2][lr] = bb.z; Bs[s ^ 1][lk + 3][lr] = bb.w;
        }
        __syncthreads();
        s ^= 1;
    }

    // fold: xin = fadd(p0, p1)
#pragma unroll
    for (int i = 0; i < 8; i++) {
        float* dst = g_xin + (size_t)(m0 + tm + i) * HH + n0 + tn;
        float4 p0a = *(const float4*)(dst + 0);
        float4 p0b = *(const float4*)(dst + 4);
        float4 oa, ob;
        oa.x = __fadd_rn(p0a.x, acc[i][0]); oa.y = __fadd_rn(p0a.y, acc[i][1]);
        oa.z = __fadd_rn(p0a.z, acc[i][2]); oa.w = __fadd_rn(p0a.w, acc[i][3]);
        ob.x = __fadd_rn(p0b.x, acc[i][4]); ob.y = __fadd_rn(p0b.y, acc[i][5]);
        ob.z = __fadd_rn(p0b.z, acc[i][6]); ob.w = __fadd_rn(p0b.w, acc[i][7]);
        *(float4*)(dst + 0) = oa;
        *(float4*)(dst + 4) = ob;
    }
}

// ============================================================
// persistent per-batch-row kernel: block b runs ALL 127 steps
// (recurrence is per-b independent), then softmaxes its 128 rows.
// Bit-exact v-path: sequential fadd over ascending active j with
// panel folds at 320/640/960; v = fma(a,v,rec)+xin-z.
// ============================================================
__global__ void __launch_bounds__(256) step_all(const float* __restrict__ w_out,
                                                float* __restrict__ out) {
    const int b = blockIdx.x;
    const int tid = threadIdx.x;
    const int lane = tid & 31, wid = tid >> 5;
    const int h4 = tid * 4;

    __shared__ int lists[2][HH];
    __shared__ int s_po[5];
    __shared__ int s_wsum[8], s_woff[8];
    __shared__ int s_total;
    __shared__ float s_red[OO][9];

    float v0 = 0.f, v1 = 0.f, v2 = 0.f, v3 = 0.f;
    float vo = 0.f;                          // valid for tid < OO

    if (tid < 5) s_po[tid] = 0;
    if (tid < OO) out[(size_t)b * OO + tid] = 0.f;   // row t=0
    __syncthreads();

    for (int t = 0; t < T_STEPS; t++) {
        // gate on input-GEMM chunk availability
        if ((t & (TCHUNK - 1)) == 0) {
            if (tid == 0) {
                const int need = (t >> 4) + 1;
                while (*((volatile int*)&g_ready) < need) __nanosleep(200);
            }
            __syncthreads();
        }

        const int* act = lists[t & 1];
        int* nxt = lists[(t + 1) & 1];

        // ---- sparse recurrent sum: exact per-panel chains, MLP-8 ----
        float tot0 = 0.f, tot1 = 0.f, tot2 = 0.f, tot3 = 0.f;
#pragma unroll 1
        for (int p = 0; p < 4; p++) {
            const int beg = s_po[p], end = s_po[p + 1];
            float a0 = 0.f, a1 = 0.f, a2 = 0.f, a3 = 0.f;
            int i = beg;
            for (; i + 8 <= end; i += 8) {
                float4 w[8];
#pragma unroll
                for (int q = 0; q < 8; q++)
                    w[q] = *(const float4*)(g_WT + (size_t)act[i + q] * HH + h4);
#pragma unroll
                for (int q = 0; q < 8; q++) {
                    a0 = __fadd_rn(a0, w[q].x);
                    a1 = __fadd_rn(a1, w[q].y);
                    a2 = __fadd_rn(a2, w[q].z);
                    a3 = __fadd_rn(a3, w[q].w);
                }
            }
            for (; i < end; i++) {
                const float4 w = *(const float4*)(g_WT + (size_t)act[i] * HH + h4);
                a0 = __fadd_rn(a0, w.x);
                a1 = __fadd_rn(a1, w.y);
                a2 = __fadd_rn(a2, w.z);
                a3 = __fadd_rn(a3, w.w);
            }
            tot0 = __fadd_rn(tot0, a0);
            tot1 = __fadd_rn(tot1, a1);
            tot2 = __fadd_rn(tot2, a2);
            tot3 = __fadd_rn(tot3, a3);
        }

        // ---- v update ----
        const float4 xi = *(const float4*)(g_xin + (size_t)t * BSZ * HH + (size_t)b * HH + h4);
        const float zp0 = (v0 > THRv) ? 1.f : 0.f;
        const float zp1 = (v1 > THRv) ? 1.f : 0.f;
        const float zp2 = (v2 > THRv) ? 1.f : 0.f;
        const float zp3 = (v3 > THRv) ? 1.f : 0.f;

        v0 = __fsub_rn(__fadd_rn(__fmaf_rn(c_ALPHA, v0, tot0), xi.x), zp0);
        v1 = __fsub_rn(__fadd_rn(__fmaf_rn(c_ALPHA, v1, tot1), xi.y), zp1);
        v2 = __fsub_rn(__fadd_rn(__fmaf_rn(c_ALPHA, v2, tot2), xi.z), zp2);
        v3 = __fsub_rn(__fadd_rn(__fmaf_rn(c_ALPHA, v3, tot3), xi.w), zp3);

        const bool z0 = v0 > THRv, z1 = v1 > THRv, z2 = v2 > THRv, z3 = v3 > THRv;
        const int cnt = (int)z0 + (int)z1 + (int)z2 + (int)z3;

        // ---- ordered block scan -> ascending active list for t+1 ----
        int s = cnt;
#pragma unroll
        for (int o = 1; o < 32; o <<= 1) {
            int u = __shfl_up_sync(0xffffffffu, s, o);
            if (lane >= o) s += u;
        }
        if (lane == 31) s_wsum[wid] = s;
        __syncthreads();                  // also: all gathers done before s_po rewrite
        if (wid == 0 && lane < 8) {
            int u = s_wsum[lane];
            int sc = u;
#pragma unroll
            for (int o = 1; o < 8; o <<= 1) {
                int q = __shfl_up_sync(0xffu, sc, o);
                if (lane >= o) sc += q;
            }
            s_woff[lane] = sc - u;
            if (lane == 7) s_total = sc;
        }
        __syncthreads();

        int o = s_woff[wid] + s - cnt;
        if (z0) nxt[o++] = h4 + 0;
        if (z1) nxt[o++] = h4 + 1;
        if (z2) nxt[o++] = h4 + 2;
        if (z3) nxt[o++] = h4 + 3;

        const int incl = s_woff[wid] + s;
        if (tid == 79)  s_po[1] = incl;       // h < 320
        if (tid == 159) s_po[2] = incl;       // h < 640
        if (tid == 239) s_po[3] = incl;       // h < 960
        if (tid == 255) { s_po[4] = incl; s_po[0] = 0; }
        __syncthreads();

        // ---- output projection over new spikes (order-free) ----
        const int total = s_total;
        if (tid < OO * 8) {
            const int oo = tid >> 3, c = tid & 7;
            const float* wr = w_out + (size_t)oo * HH;
            float acc = 0.f;
            for (int i = c; i < total; i += 8)
                acc += wr[nxt[i]];
            s_red[oo][c] = acc;
        }
        __syncthreads();
        if (tid < OO) {
            float ssum = s_red[tid][0];
#pragma unroll
            for (int c = 1; c < 8; c++) ssum += s_red[tid][c];
            vo = __fmaf_rn(c_KAPPA, vo, ssum);
            out[((size_t)(t + 1) * BSZ + b) * OO + tid] = vo;
        }
        __syncthreads();
    }

    // ---- softmax of this b's 128 rows (warp per row) ----
    __syncthreads();
    for (int r = wid; r < T_ALL; r += 8) {
        float* pr = out + ((size_t)r * BSZ + b) * OO;
        float vv = (lane < OO) ? pr[lane] : -INFINITY;
        float m = vv;
#pragma unroll
        for (int off = 16; off > 0; off >>= 1)
            m = fmaxf(m, __shfl_xor_sync(0xffffffff, m, off));
        float e = (lane < OO) ? expf(vv - m) : 0.f;
        float sm = e;
#pragma unroll
        for (int off = 16; off > 0; off >>= 1)
            sm += __shfl_xor_sync(0xffffffff, sm, off);
        if (lane < OO) pr[lane] = e / sm;
    }
}

// ============================================================
extern "C" void kernel_launch(void* const* d_in, const int* in_sizes, int n_in,
                              void* d_out, int out_size) {
    const float* x     = (const float*)d_in[0];  // [128,256,512]
    const float* w_in  = (const float*)d_in[1];  // [1024,512]
    const float* w_rec = (const float*)d_in[2];  // [1024,1024]
    const float* w_out = (const float*)d_in[3];  // [20,1024]
    float* out = (float*)d_out;                  // [128,256,20]

    static cudaStream_t s2 = nullptr;
    static cudaEvent_t eF = nullptr, eJ = nullptr;
    if (!s2) {
        cudaStreamCreateWithFlags(&s2, cudaStreamNonBlocking);
        cudaEventCreateWithFlags(&eF, cudaEventDisableTiming);
        cudaEventCreateWithFlags(&eJ, cudaEventDisableTiming);
    }

    set_flag<<<1, 1>>>(0);                       // reset chunk flag (per launch)
    prep_k<<<512, 256>>>(w_rec);

    // fork: input-GEMM chunks on side stream
    cudaEventRecord(eF, 0);
    cudaStreamWaitEvent(s2, eF, 0);
    for (int c = 0; c < 8; c++) {
        const int tcnt = (c == 7) ? (T_STEPS - 7 * TCHUNK) : TCHUNK;   // 15 for last
        const int yblocks = (tcnt * BSZ) / 128;
        in_gemm<<<dim3(HH / 128, yblocks), 256, 0, s2>>>(x, w_in, c * TCHUNK * BSZ);
        marker<<<1, 1, 0, s2>>>(c + 1);
    }
    cudaEventRecord(eJ, s2);

    // persistent recurrent scan (overlaps with in_gemm via flag gating)
    step_all<<<BSZ, 256>>>(w_out, out);

    cudaStreamWaitEvent(0, eJ, 0);               // join side stream into capture
}